// round 9
// baseline (speedup 1.0000x reference)
#include <cuda_runtime.h>
#include <math.h>

#define NHEADS 16
#define HSIZE  64
#define NG     8
#define B_     8
#define T_     2048
#define C_     1024
#define GT     256
#define GT1    257

// ---------------- scratch (device globals: no allocation allowed) -------------
__device__ float g_qkv[(size_t)B_ * T_ * 3 * C_];        // 201 MB
__device__ float g_xo [(size_t)B_ * T_ * C_];            // 67 MB
__device__ float g_mean[3][B_][NHEADS][NG][HSIZE];       // q/k/v group means
__device__ float g_attmean[B_][NHEADS][NG][HSIZE];       // attn1 output at mean rows

// ---------------- TF32 tensor-core GEMM (double-buffered) ---------------------
// C[M,N] = A[M,K] * B[K,N], row-major. Block tile 128x128, K-chunk 32.
// 8 warps: warp tile 64x32 from 4x4 mma.m16n8k8.tf32. 2 smem buffers +
// register prefetch: one __syncthreads per K-chunk, loads overlap mma.

#define AS_STRIDE 36
#define BS_STRIDE 136
#define AS_BUF (128 * AS_STRIDE)   // 4608 floats
#define BS_BUF (32 * BS_STRIDE)    // 4352 floats
#define GEMM_SMEM ((2 * (AS_BUF + BS_BUF)) * (int)sizeof(float))   // 71680 B

__device__ __forceinline__ float to_tf32(float x) {
    float y;
    asm("cvt.rna.tf32.f32 %0, %1;" : "=f"(y) : "f"(x));
    return y;
}

__device__ __forceinline__ void mma_tf32(float* c, const float* a, const float* b) {
    asm volatile(
        "mma.sync.aligned.m16n8k8.row.col.f32.tf32.tf32.f32 "
        "{%0,%1,%2,%3}, {%4,%5,%6,%7}, {%8,%9}, {%0,%1,%2,%3};\n"
        : "+f"(c[0]), "+f"(c[1]), "+f"(c[2]), "+f"(c[3])
        : "r"(__float_as_uint(a[0])), "r"(__float_as_uint(a[1])),
          "r"(__float_as_uint(a[2])), "r"(__float_as_uint(a[3])),
          "r"(__float_as_uint(b[0])), "r"(__float_as_uint(b[1])));
}

__global__ __launch_bounds__(256) void tf32gemm_kernel(
    int M, int N, int K,
    const float* __restrict__ A, const float* __restrict__ B, float* __restrict__ C)
{
    extern __shared__ float smem_dyn[];
    float* As = smem_dyn;                 // [2][128][36]
    float* Bs = smem_dyn + 2 * AS_BUF;    // [2][32][136]

    const int tid  = threadIdx.x;
    const int lane = tid & 31;
    const int warp = tid >> 5;
    const int warpRow = (warp & 1) * 64;   // m offset of warp tile
    const int warpCol = (warp >> 1) * 32;  // n offset of warp tile
    const int g = lane >> 2;               // groupID
    const int t = lane & 3;                // threadID_in_group

    A += (size_t)blockIdx.y * 128 * K;
    B += blockIdx.x * 128;
    C += (size_t)blockIdx.y * 128 * N + blockIdx.x * 128;

    float acc[4][4][4];
    #pragma unroll
    for (int i = 0; i < 4; i++)
        #pragma unroll
        for (int j = 0; j < 4; j++)
            #pragma unroll
            for (int r = 0; r < 4; r++) acc[i][j][r] = 0.f;

    const int aRow = tid >> 3;          // 0..31 (4 passes of 32 rows)
    const int aCol = (tid & 7) * 4;     // 0..28
    const int bRow = tid >> 5;          // 0..7  (4 passes of 8 rows)
    const int bCol = (tid & 31) * 4;    // 0..124

    float4 pa[4], pb[4];

    // prologue: fetch chunk 0, stage into buffer 0
    #pragma unroll
    for (int i = 0; i < 4; i++)
        pa[i] = *(const float4*)(&A[(size_t)(aRow + 32 * i) * K + aCol]);
    #pragma unroll
    for (int i = 0; i < 4; i++)
        pb[i] = *(const float4*)(&B[(size_t)(bRow + 8 * i) * N + bCol]);

    {
        #pragma unroll
        for (int i = 0; i < 4; i++) {
            float* a = As + (aRow + 32 * i) * AS_STRIDE + aCol;
            a[0] = to_tf32(pa[i].x); a[1] = to_tf32(pa[i].y);
            a[2] = to_tf32(pa[i].z); a[3] = to_tf32(pa[i].w);
            float* bp = Bs + (bRow + 8 * i) * BS_STRIDE + bCol;
            bp[0] = to_tf32(pb[i].x); bp[1] = to_tf32(pb[i].y);
            bp[2] = to_tf32(pb[i].z); bp[3] = to_tf32(pb[i].w);
        }
    }
    __syncthreads();

    int buf = 0;
    for (int k0 = 0; k0 < K; k0 += 32) {
        const bool more = (k0 + 32) < K;
        if (more) {   // prefetch next chunk into registers (overlaps mma below)
            #pragma unroll
            for (int i = 0; i < 4; i++)
                pa[i] = *(const float4*)(&A[(size_t)(aRow + 32 * i) * K + (k0 + 32) + aCol]);
            #pragma unroll
            for (int i = 0; i < 4; i++)
                pb[i] = *(const float4*)(&B[(size_t)(k0 + 32 + bRow + 8 * i) * N + bCol]);
        }

        const float* Ab = As + buf * AS_BUF;
        const float* Bb = Bs + buf * BS_BUF;
        #pragma unroll
        for (int kk = 0; kk < 32; kk += 8) {
            float afr[4][4];
            #pragma unroll
            for (int mt = 0; mt < 4; mt++) {
                const int r = warpRow + mt * 16;
                afr[mt][0] = Ab[(r + g    ) * AS_STRIDE + kk + t    ];
                afr[mt][1] = Ab[(r + g + 8) * AS_STRIDE + kk + t    ];
                afr[mt][2] = Ab[(r + g    ) * AS_STRIDE + kk + t + 4];
                afr[mt][3] = Ab[(r + g + 8) * AS_STRIDE + kk + t + 4];
            }
            float bfr[4][2];
            #pragma unroll
            for (int nt = 0; nt < 4; nt++) {
                const int c = warpCol + nt * 8 + g;
                bfr[nt][0] = Bb[(kk + t    ) * BS_STRIDE + c];
                bfr[nt][1] = Bb[(kk + t + 4) * BS_STRIDE + c];
            }
            #pragma unroll
            for (int mt = 0; mt < 4; mt++)
                #pragma unroll
                for (int nt = 0; nt < 4; nt++)
                    mma_tf32(acc[mt][nt], afr[mt], bfr[nt]);
        }

        if (more) {   // stage prefetched chunk into the other buffer
            float* Aw = As + (buf ^ 1) * AS_BUF;
            float* Bw = Bs + (buf ^ 1) * BS_BUF;
            #pragma unroll
            for (int i = 0; i < 4; i++) {
                float* a = Aw + (aRow + 32 * i) * AS_STRIDE + aCol;
                a[0] = to_tf32(pa[i].x); a[1] = to_tf32(pa[i].y);
                a[2] = to_tf32(pa[i].z); a[3] = to_tf32(pa[i].w);
                float* bp = Bw + (bRow + 8 * i) * BS_STRIDE + bCol;
                bp[0] = to_tf32(pb[i].x); bp[1] = to_tf32(pb[i].y);
                bp[2] = to_tf32(pb[i].z); bp[3] = to_tf32(pb[i].w);
            }
            __syncthreads();
            buf ^= 1;
        }
    }

    #pragma unroll
    for (int mt = 0; mt < 4; mt++) {
        const int r0 = warpRow + mt * 16 + g;
        #pragma unroll
        for (int nt = 0; nt < 4; nt++) {
            const int c0 = warpCol + nt * 8 + 2 * t;
            *(float2*)(&C[(size_t)r0 * N + c0]) =
                make_float2(acc[mt][nt][0], acc[mt][nt][1]);
            *(float2*)(&C[(size_t)(r0 + 8) * N + c0]) =
                make_float2(acc[mt][nt][2], acc[mt][nt][3]);
        }
    }
}

// ---------------- group means of q,k,v ---------------------------------------
__global__ __launch_bounds__(192) void means_kernel()
{
    const int g = blockIdx.x, h = blockIdx.y, b = blockIdx.z;
    const int which = threadIdx.x / HSIZE;   // 0=q,1=k,2=v
    const int d     = threadIdx.x % HSIZE;
    const float* base = g_qkv + (size_t)(b * T_ + g * GT) * (3 * C_)
                              + which * C_ + h * HSIZE + d;
    float s = 0.f;
    #pragma unroll 4
    for (int t = 0; t < GT; t++) s += base[(size_t)t * (3 * C_)];
    g_mean[which][b][h][g][d] = s * (1.f / GT);
}

// ---------------- attention 1: per (b,h,g), 257x257 causal --------------------
// Two threads per query row: thread owns 32 of 64 head dims; QK dot combined
// with one pair shfl per key. Softmax state duplicated per pair (identical).
#define A1_THREADS 544

__global__ __launch_bounds__(A1_THREADS, 1) void attn1_kernel()
{
    extern __shared__ float sm[];
    float* Ks = sm;                 // [257][64]
    float* Vs = sm + GT1 * HSIZE;   // [257][64]

    const int g = blockIdx.x, h = blockIdx.y, b = blockIdx.z;
    const int tid = threadIdx.x;

    for (int idx = tid; idx < GT1 * HSIZE; idx += A1_THREADS) {
        const int j = idx >> 6, d = idx & 63;
        float kk, vv;
        if (j < GT) {
            const size_t row = (size_t)(b * T_ + g * GT + j) * (3 * C_) + h * HSIZE + d;
            kk = g_qkv[row + C_];
            vv = g_qkv[row + 2 * C_];
        } else {
            kk = g_mean[1][b][h][g][d];
            vv = g_mean[2][b][h][g][d];
        }
        Ks[idx] = kk;
        Vs[idx] = vv;
    }
    __syncthreads();

    const int i = tid >> 1;
    if (i > GT) return;             // rows 0..256, pairs of lanes
    const int half = tid & 1;
    const int dofs = half << 5;     // 0 or 32
    const unsigned pmask = 3u << ((tid & 31) & 30);   // lane-pair shfl mask

    float q[32];
    if (i < GT) {
        const float* qp = g_qkv + (size_t)(b * T_ + g * GT + i) * (3 * C_)
                        + h * HSIZE + dofs;
        #pragma unroll
        for (int d4 = 0; d4 < 8; d4++) {
            float4 v = *(const float4*)(qp + 4 * d4);
            q[4 * d4 + 0] = v.x; q[4 * d4 + 1] = v.y;
            q[4 * d4 + 2] = v.z; q[4 * d4 + 3] = v.w;
        }
    } else {
        #pragma unroll
        for (int d = 0; d < 32; d++) q[d] = g_mean[0][b][h][g][dofs + d];
    }

    const int jmax = (i < GT) ? i : GT;   // causal: mean row attends everything
    float m = -1e30f, l = 0.f;
    float acc[32];
    #pragma unroll
    for (int d = 0; d < 32; d++) acc[d] = 0.f;

    for (int j = 0; j <= jmax; j++) {
        const float4* kp = (const float4*)(Ks + j * HSIZE + dofs);
        float s = 0.f;
        #pragma unroll
        for (int d4 = 0; d4 < 8; d4++) {
            float4 kv = kp[d4];
            s += q[4 * d4 + 0] * kv.x + q[4 * d4 + 1] * kv.y
               + q[4 * d4 + 2] * kv.z + q[4 * d4 + 3] * kv.w;
        }
        s += __shfl_xor_sync(pmask, s, 1);   // combine the two 32-dim partials
        s *= 0.125f;   // 1/sqrt(64)
        const float mn   = fmaxf(m, s);
        const float corr = __expf(m - mn);
        const float p    = __expf(s - mn);
        l = l * corr + p;
        const float4* vp = (const float4*)(Vs + j * HSIZE + dofs);
        #pragma unroll
        for (int d4 = 0; d4 < 8; d4++) {
            float4 vv = vp[d4];
            acc[4 * d4 + 0] = acc[4 * d4 + 0] * corr + p * vv.x;
            acc[4 * d4 + 1] = acc[4 * d4 + 1] * corr + p * vv.y;
            acc[4 * d4 + 2] = acc[4 * d4 + 2] * corr + p * vv.z;
            acc[4 * d4 + 3] = acc[4 * d4 + 3] * corr + p * vv.w;
        }
        m = mn;
    }
    const float inv = 1.f / l;

    if (i < GT) {
        float* op = g_xo + (size_t)(b * T_ + g * GT + i) * C_ + h * HSIZE + dofs;
        #pragma unroll
        for (int d4 = 0; d4 < 8; d4++) {
            float4 v = make_float4(acc[4 * d4 + 0] * inv, acc[4 * d4 + 1] * inv,
                                   acc[4 * d4 + 2] * inv, acc[4 * d4 + 3] * inv);
            *(float4*)(op + 4 * d4) = v;
        }
    } else {
        #pragma unroll
        for (int d = 0; d < 32; d++) g_attmean[b][h][g][dofs + d] = acc[d] * inv;
    }
}

// ---------------- attention 2 (7x7 over group means) + y outputs --------------
__global__ __launch_bounds__(64) void attn2_kernel(float* __restrict__ out)
{
    __shared__ float qs[7 * 64], ks[7 * 64], vs[7 * 64];
    const int h = blockIdx.x, b = blockIdx.y;
    const int tid = threadIdx.x;   // 64 threads = one d each

    for (int g = 0; g < 7; g++) {
        qs[g * 64 + tid] = g_mean[0][b][h][g][tid];
        ks[g * 64 + tid] = g_mean[1][b][h][g][tid];
        vs[g * 64 + tid] = g_attmean[b][h][g][tid];
    }
    __syncthreads();

    const size_t YQ   = (size_t)B_ * T_ * C_;                 // 16777216
    const size_t YLEN = (size_t)B_ * NHEADS * 7 * HSIZE;      // 57344
    for (int g = 0; g < 7; g++) {
        const size_t o = ((size_t)(b * NHEADS + h) * 7 + g) * HSIZE + tid;
        out[YQ + o]        = qs[g * 64 + tid];   // yq
        out[YQ + YLEN + o] = ks[g * 64 + tid];   // yk
    }

    if (tid < 7) {
        const int i = tid;
        float sc[7];
        float m = -1e30f;
        for (int j = 0; j <= i; j++) {
            float s = 0.f;
            #pragma unroll
            for (int d = 0; d < 64; d++) s += qs[i * 64 + d] * ks[j * 64 + d];
            s *= 0.125f;
            sc[j] = s;
            m = fmaxf(m, s);
        }
        float l = 0.f;
        for (int j = 0; j <= i; j++) { sc[j] = __expf(sc[j] - m); l += sc[j]; }
        const float inv = 1.f / l;
        for (int d = 0; d < 64; d++) {
            float a = 0.f;
            for (int j = 0; j <= i; j++) a += sc[j] * vs[j * 64 + d];
            out[YQ + 2 * YLEN + ((size_t)(b * NHEADS + h) * 7 + i) * HSIZE + d] = a * inv;
        }
    }
}

// ---------------- launch ------------------------------------------------------
extern "C" void kernel_launch(void* const* d_in, const int* in_sizes, int n_in,
                              void* d_out, int out_size)
{
    const float* x      = (const float*)d_in[0];
    const float* W_attn = (const float*)d_in[1];
    const float* W_proj = (const float*)d_in[2];
    float* out = (float*)d_out;

    static float* p_qkv = nullptr;
    static float* p_xo  = nullptr;
    if (!p_qkv) {   // first call is the (uncaptured) correctness run
        cudaGetSymbolAddress((void**)&p_qkv, g_qkv);
        cudaGetSymbolAddress((void**)&p_xo,  g_xo);
        cudaFuncSetAttribute(attn1_kernel,
            cudaFuncAttributeMaxDynamicSharedMemorySize,
            2 * GT1 * HSIZE * (int)sizeof(float));
        cudaFuncSetAttribute(tf32gemm_kernel,
            cudaFuncAttributeMaxDynamicSharedMemorySize, GEMM_SMEM);
    }

    // 1) qkv = x @ W_attn   [16384,1024] x [1024,3072]  (TF32 tensor cores)
    {
        dim3 grid((3 * C_) / 128, (B_ * T_) / 128);
        tf32gemm_kernel<<<grid, 256, GEMM_SMEM>>>(B_ * T_, 3 * C_, C_, x, W_attn, p_qkv);
    }
    // 2) group means of q,k,v
    means_kernel<<<dim3(NG, NHEADS, B_), 192>>>();
    // 3) grouped causal attention (writes g_xo + g_attmean)
    attn1_kernel<<<dim3(NG, NHEADS, B_), A1_THREADS,
                   2 * GT1 * HSIZE * sizeof(float)>>>();
    // 4) group-summary attention + yq/yk/yv
    attn2_kernel<<<dim3(NHEADS, B_), 64>>>(out);
    // 5) out = xo @ W_proj  [16384,1024] x [1024,1024]  (TF32 tensor cores)
    {
        dim3 grid(C_ / 128, (B_ * T_) / 128);
        tf32gemm_kernel<<<grid, 256, GEMM_SMEM>>>(B_ * T_, C_, C_, p_xo, W_proj, out);
    }
}